// round 1
// baseline (speedup 1.0000x reference)
#include <cuda_runtime.h>

#define NN 100000
#define NE 1600000
#define NF 128
#define NH 64
#define NC 40

#define SCAN_B 1024
#define NBLK ((NN + SCAN_B - 1) / SCAN_B)   // 98

// ---------------- scratch (static device globals; no allocation) ----------------
__device__ int   g_is64;
__device__ int   g_src[NE];
__device__ int   g_dst[NE];
__device__ float g_degw[NN];
__device__ int   g_cnt[NN];
__device__ int   g_rowptr[NN];
__device__ int   g_fill[NN];
__device__ float g_dinv[NN];
__device__ int   g_srcs[NE];       // CSR-sorted src ids
__device__ float g_normv[NE];      // CSR-sorted norm coefficients
__device__ float g_h1[NN * NH];
__device__ float g_a1[NN * NH];
__device__ float g_h2[NN * NC];
__device__ int   g_bsum[NBLK];

// ---------------- dtype detection (int64 vs int32 edge_index) ----------------
__global__ void k_detect(const long long* __restrict__ ei) {
    __shared__ int ok;
    if (threadIdx.x == 0) ok = 1;
    __syncthreads();
    long long v = ei[threadIdx.x];   // 256 leading values
    if (!(v >= 0 && v < (long long)NN)) atomicAnd(&ok, 0);
    __syncthreads();
    if (threadIdx.x == 0) g_is64 = ok;
}

__global__ void k_decode(const void* __restrict__ ei) {
    int e = blockIdx.x * blockDim.x + threadIdx.x;
    if (e >= NE) return;
    if (g_is64) {
        const long long* p = (const long long*)ei;
        g_src[e] = (int)p[e];
        g_dst[e] = (int)p[NE + e];
    } else {
        const int* p = (const int*)ei;
        g_src[e] = p[e];
        g_dst[e] = p[NE + e];
    }
}

// ---------------- degree / dinv ----------------
__global__ void k_init_nodes() {
    int i = blockIdx.x * blockDim.x + threadIdx.x;
    if (i >= NN) return;
    g_degw[i] = 1.0f;   // self-loop weight
    g_cnt[i]  = 0;
}

__global__ void k_edge_deg(const float* __restrict__ w) {
    int e = blockIdx.x * blockDim.x + threadIdx.x;
    if (e >= NE) return;
    int d = g_dst[e];
    atomicAdd(&g_degw[d], w[e]);
    atomicAdd(&g_cnt[d], 1);
}

__global__ void k_dinv() {
    int i = blockIdx.x * blockDim.x + threadIdx.x;
    if (i >= NN) return;
    g_dinv[i] = rsqrtf(g_degw[i]);   // degw >= 1 always
}

// ---------------- exclusive scan over g_cnt -> g_rowptr ----------------
__global__ void k_scan1() {
    __shared__ int s[SCAN_B];
    int gid = blockIdx.x * SCAN_B + threadIdx.x;
    int v = (gid < NN) ? g_cnt[gid] : 0;
    s[threadIdx.x] = v;
    __syncthreads();
    for (int off = 1; off < SCAN_B; off <<= 1) {
        int t = (threadIdx.x >= off) ? s[threadIdx.x - off] : 0;
        __syncthreads();
        s[threadIdx.x] += t;
        __syncthreads();
    }
    int incl = s[threadIdx.x];
    if (gid < NN) g_rowptr[gid] = incl - v;          // exclusive
    if (threadIdx.x == SCAN_B - 1) g_bsum[blockIdx.x] = incl;
}

__global__ void k_scan2() {
    if (threadIdx.x == 0) {
        int run = 0;
        for (int b = 0; b < NBLK; b++) {
            int t = g_bsum[b];
            g_bsum[b] = run;
            run += t;
        }
    }
}

__global__ void k_scan3() {
    int gid = blockIdx.x * SCAN_B + threadIdx.x;
    if (gid >= NN) return;
    int rp = g_rowptr[gid] + g_bsum[blockIdx.x];
    g_rowptr[gid] = rp;
    g_fill[gid]   = rp;
}

// ---------------- CSR fill ----------------
__global__ void k_fill(const float* __restrict__ w) {
    int e = blockIdx.x * blockDim.x + threadIdx.x;
    if (e >= NE) return;
    int s = g_src[e], d = g_dst[e];
    int pos = atomicAdd(&g_fill[d], 1);
    g_srcs[pos]  = s;
    g_normv[pos] = g_dinv[s] * w[e] * g_dinv[d];
}

// ---------------- GEMM1: h1 = x @ W1   [NN,128]x[128,64] ----------------
__global__ __launch_bounds__(256) void k_gemm1(const float* __restrict__ x,
                                               const float* __restrict__ W1) {
    __shared__ float Ws[NF * NH];    // 32 KB
    __shared__ float xs[32 * NF];    // 16 KB
    int tid = threadIdx.x;
    int row0 = blockIdx.x * 32;

    const float4* W4 = (const float4*)W1;
    float4* Ws4 = (float4*)Ws;
    #pragma unroll
    for (int i = tid; i < (NF * NH) / 4; i += 256) Ws4[i] = W4[i];

    const float4* x4 = (const float4*)(x + (size_t)row0 * NF);
    float4* xs4 = (float4*)xs;
    #pragma unroll
    for (int i = tid; i < 32 * NF / 4; i += 256) xs4[i] = x4[i];
    __syncthreads();

    int r = tid >> 3;        // 0..31
    int cg = tid & 7;        // 8 cols each
    float acc[8] = {0.f, 0.f, 0.f, 0.f, 0.f, 0.f, 0.f, 0.f};
    const float* xr = &xs[r * NF];
    #pragma unroll 4
    for (int k = 0; k < NF; k++) {
        float xv = xr[k];
        float4 w0 = *(const float4*)&Ws[k * NH + cg * 8];
        float4 w1 = *(const float4*)&Ws[k * NH + cg * 8 + 4];
        acc[0] += xv * w0.x; acc[1] += xv * w0.y;
        acc[2] += xv * w0.z; acc[3] += xv * w0.w;
        acc[4] += xv * w1.x; acc[5] += xv * w1.y;
        acc[6] += xv * w1.z; acc[7] += xv * w1.w;
    }
    float* o = g_h1 + (size_t)(row0 + r) * NH + cg * 8;
    *(float4*)o       = make_float4(acc[0], acc[1], acc[2], acc[3]);
    *(float4*)(o + 4) = make_float4(acc[4], acc[5], acc[6], acc[7]);
}

// ---------------- AGG1 (gather) + bias + relu : warp per node ----------------
__global__ __launch_bounds__(256) void k_agg1(const float* __restrict__ b1) {
    int node = (blockIdx.x * blockDim.x + threadIdx.x) >> 5;
    int lane = threadIdx.x & 31;
    if (node >= NN) return;
    int beg = g_rowptr[node];
    int end = beg + g_cnt[node];
    float di = g_dinv[node];
    float self = di * di;
    const float* h1n = &g_h1[(size_t)node * NH];
    float a0 = self * h1n[lane];
    float a1 = self * h1n[32 + lane];

    int e = beg;
    for (; e + 1 < end; e += 2) {
        int s0 = g_srcs[e];     float n0 = g_normv[e];
        int s1 = g_srcs[e + 1]; float n1 = g_normv[e + 1];
        const float* p0 = &g_h1[(size_t)s0 * NH];
        const float* p1 = &g_h1[(size_t)s1 * NH];
        float v00 = p0[lane], v01 = p0[32 + lane];
        float v10 = p1[lane], v11 = p1[32 + lane];
        a0 += n0 * v00; a1 += n0 * v01;
        a0 += n1 * v10; a1 += n1 * v11;
    }
    if (e < end) {
        int s0 = g_srcs[e]; float n0 = g_normv[e];
        const float* p0 = &g_h1[(size_t)s0 * NH];
        a0 += n0 * p0[lane]; a1 += n0 * p0[32 + lane];
    }
    a0 += b1[lane];
    a1 += b1[32 + lane];
    g_a1[(size_t)node * NH + lane]      = fmaxf(a0, 0.f);
    g_a1[(size_t)node * NH + 32 + lane] = fmaxf(a1, 0.f);
}

// ---------------- GEMM2: h2 = a1 @ W2   [NN,64]x[64,40] ----------------
__global__ __launch_bounds__(256) void k_gemm2(const float* __restrict__ W2) {
    __shared__ float Ws[NH * NC];    // 10 KB
    __shared__ float as[32 * NH];    // 8 KB
    int tid = threadIdx.x;
    int row0 = blockIdx.x * 32;

    for (int i = tid; i < NH * NC; i += 256) Ws[i] = W2[i];
    const float4* a4 = (const float4*)(g_a1 + (size_t)row0 * NH);
    float4* as4 = (float4*)as;
    for (int i = tid; i < 32 * NH / 4; i += 256) as4[i] = a4[i];
    __syncthreads();

    int r = tid >> 3;     // 0..31
    int cg = tid & 7;     // 5 cols each
    float acc[5] = {0.f, 0.f, 0.f, 0.f, 0.f};
    const float* ar = &as[r * NH];
    #pragma unroll 4
    for (int k = 0; k < NH; k++) {
        float av = ar[k];
        const float* wk = &Ws[k * NC + cg * 5];
        #pragma unroll
        for (int j = 0; j < 5; j++) acc[j] += av * wk[j];
    }
    float* o = g_h2 + (size_t)(row0 + r) * NC + cg * 5;
    #pragma unroll
    for (int j = 0; j < 5; j++) o[j] = acc[j];
}

// ---------------- AGG2 (gather) + bias + log_softmax : warp per node ----------------
__global__ __launch_bounds__(256) void k_agg2(const float* __restrict__ b2,
                                              float* __restrict__ out) {
    int node = (blockIdx.x * blockDim.x + threadIdx.x) >> 5;
    int lane = threadIdx.x & 31;
    if (node >= NN) return;
    bool hi = (lane < NC - 32);    // lanes 0..7 own cols 32..39
    int beg = g_rowptr[node];
    int end = beg + g_cnt[node];
    float di = g_dinv[node];
    float self = di * di;
    const float* h2n = &g_h2[(size_t)node * NC];
    float a0 = self * h2n[lane];
    float a1 = hi ? self * h2n[32 + lane] : 0.f;

    int e = beg;
    for (; e + 1 < end; e += 2) {
        int s0 = g_srcs[e];     float n0 = g_normv[e];
        int s1 = g_srcs[e + 1]; float n1 = g_normv[e + 1];
        const float* p0 = &g_h2[(size_t)s0 * NC];
        const float* p1 = &g_h2[(size_t)s1 * NC];
        a0 += n0 * p0[lane];
        a0 += n1 * p1[lane];
        if (hi) {
            a1 += n0 * p0[32 + lane];
            a1 += n1 * p1[32 + lane];
        }
    }
    if (e < end) {
        int s0 = g_srcs[e]; float n0 = g_normv[e];
        const float* p0 = &g_h2[(size_t)s0 * NC];
        a0 += n0 * p0[lane];
        if (hi) a1 += n0 * p0[32 + lane];
    }
    a0 += b2[lane];
    if (hi) a1 += b2[32 + lane];

    // log_softmax over the 40 values held by this warp
    float m = hi ? fmaxf(a0, a1) : a0;
    #pragma unroll
    for (int off = 16; off > 0; off >>= 1)
        m = fmaxf(m, __shfl_xor_sync(0xffffffffu, m, off));
    float s = __expf(a0 - m) + (hi ? __expf(a1 - m) : 0.f);
    #pragma unroll
    for (int off = 16; off > 0; off >>= 1)
        s += __shfl_xor_sync(0xffffffffu, s, off);
    float lse = m + __logf(s);

    float* o = out + (size_t)node * NC;
    o[lane] = a0 - lse;
    if (hi) o[32 + lane] = a1 - lse;
}

// ---------------- launcher ----------------
extern "C" void kernel_launch(void* const* d_in, const int* in_sizes, int n_in,
                              void* d_out, int out_size) {
    const float* x  = (const float*)d_in[0];
    const void*  ei = d_in[1];
    const float* ew = (const float*)d_in[2];
    const float* W1 = (const float*)d_in[3];
    const float* b1 = (const float*)d_in[4];
    const float* W2 = (const float*)d_in[5];
    const float* b2 = (const float*)d_in[6];
    float* out = (float*)d_out;

    const int EB = (NE + 255) / 256;    // 6250
    const int VB = (NN + 255) / 256;    // 391
    const int GB = NN / 32;             // 3125 (exact)
    const int AB = (NN * 32 + 255) / 256; // 12500 warps->blocks

    k_detect<<<1, 256>>>((const long long*)ei);
    k_decode<<<EB, 256>>>(ei);
    k_init_nodes<<<VB, 256>>>();
    k_edge_deg<<<EB, 256>>>(ew);
    k_dinv<<<VB, 256>>>();
    k_scan1<<<NBLK, SCAN_B>>>();
    k_scan2<<<1, 32>>>();
    k_scan3<<<NBLK, SCAN_B>>>();
    k_fill<<<EB, 256>>>(ew);
    k_gemm1<<<GB, 256>>>(x, W1);
    k_agg1<<<AB, 256>>>(b1);
    k_gemm2<<<GB, 256>>>(W2);
    k_agg2<<<AB, 256>>>(b2, out);
}

// round 2
// speedup vs baseline: 1.4298x; 1.4298x over previous
#include <cuda_runtime.h>

#define NN 100000
#define NE 1600000
#define NF 128
#define NH 64
#define NC 40

#define SCAN_B 1024
#define NBLK ((NN + SCAN_B - 1) / SCAN_B)   // 98

#define XS_STRIDE (NF + 4)   // padded to break bank conflicts
#define AS_STRIDE (NH + 4)
#define WT_STRIDE (NH + 4)

// ---------------- scratch (static device globals; no allocation) ----------------
__device__ int   g_is64;
__device__ int   g_src[NE];
__device__ int   g_dst[NE];
__device__ float g_degw[NN];
__device__ int   g_cnt[NN];
__device__ int   g_rowptr[NN];
__device__ int   g_fill[NN];
__device__ float g_dinv[NN];
__device__ int2  g_edge[NE];       // CSR: {src, float_bits(norm)}
__device__ float g_h1[NN * NH];
__device__ float g_a1[NN * NH];
__device__ float g_h2[NN * NC];
__device__ int   g_bsum[NBLK];

// ---------------- dtype detection (int64 vs int32 edge_index) ----------------
__global__ void k_detect(const long long* __restrict__ ei) {
    __shared__ int ok;
    if (threadIdx.x == 0) ok = 1;
    __syncthreads();
    long long v = ei[threadIdx.x];
    if (!(v >= 0 && v < (long long)NN)) atomicAnd(&ok, 0);
    __syncthreads();
    if (threadIdx.x == 0) g_is64 = ok;
}

// ---------------- fused decode + degree/count ----------------
__global__ void k_decode_deg(const void* __restrict__ ei, const float* __restrict__ w) {
    int e = blockIdx.x * blockDim.x + threadIdx.x;
    if (e >= NE) return;
    int s, d;
    if (g_is64) {
        const long long* p = (const long long*)ei;
        s = (int)p[e]; d = (int)p[NE + e];
    } else {
        const int* p = (const int*)ei;
        s = p[e]; d = p[NE + e];
    }
    g_src[e] = s;
    g_dst[e] = d;
    atomicAdd(&g_degw[d], w[e]);
    atomicAdd(&g_cnt[d], 1);
}

// ---------------- exclusive scan over g_cnt -> g_rowptr ----------------
__global__ void k_scan1() {
    __shared__ int s[SCAN_B];
    int gid = blockIdx.x * SCAN_B + threadIdx.x;
    int v = (gid < NN) ? g_cnt[gid] : 0;
    s[threadIdx.x] = v;
    __syncthreads();
    for (int off = 1; off < SCAN_B; off <<= 1) {
        int t = (threadIdx.x >= off) ? s[threadIdx.x - off] : 0;
        __syncthreads();
        s[threadIdx.x] += t;
        __syncthreads();
    }
    int incl = s[threadIdx.x];
    if (gid < NN) g_rowptr[gid] = incl - v;
    if (threadIdx.x == SCAN_B - 1) g_bsum[blockIdx.x] = incl;
}

__global__ void k_scan2() {
    if (threadIdx.x == 0) {
        int run = 0;
        for (int b = 0; b < NBLK; b++) {
            int t = g_bsum[b];
            g_bsum[b] = run;
            run += t;
        }
    }
}

// scan3 + dinv fused (self-loop weight folded in as +1)
__global__ void k_scan3() {
    int gid = blockIdx.x * SCAN_B + threadIdx.x;
    if (gid >= NN) return;
    int rp = g_rowptr[gid] + g_bsum[blockIdx.x];
    g_rowptr[gid] = rp;
    g_fill[gid]   = rp;
    g_dinv[gid]   = rsqrtf(g_degw[gid] + 1.0f);
}

// ---------------- CSR fill (interleaved {src, norm}) ----------------
__global__ void k_fill(const float* __restrict__ w) {
    int e = blockIdx.x * blockDim.x + threadIdx.x;
    if (e >= NE) return;
    int s = g_src[e], d = g_dst[e];
    int pos = atomicAdd(&g_fill[d], 1);
    float nv = g_dinv[s] * w[e] * g_dinv[d];
    g_edge[pos] = make_int2(s, __float_as_int(nv));
}

// ---------------- GEMM1: h1 = x @ W1  (64 rows/block, 2 rows x 8 cols/thread) ----
__global__ __launch_bounds__(256) void k_gemm1(const float* __restrict__ x,
                                               const float* __restrict__ W1) {
    __shared__ float Ws[NF * NH];            // 32 KB
    __shared__ float xs[64 * XS_STRIDE];     // ~33 KB, padded rows
    int tid = threadIdx.x;
    int row0 = blockIdx.x * 64;

    const float4* W4 = (const float4*)W1;
    float4* Ws4 = (float4*)Ws;
    #pragma unroll
    for (int i = tid; i < (NF * NH) / 4; i += 256) Ws4[i] = W4[i];

    const float4* x4 = (const float4*)x;
    int base4 = row0 * (NF / 4);
    int limit4 = (NN - row0) * (NF / 4);
    #pragma unroll
    for (int i = tid; i < 64 * (NF / 4); i += 256) {
        int rr = i >> 5;          // i / 32
        int cc = i & 31;
        float4 v = (i < limit4) ? x4[base4 + i] : make_float4(0.f, 0.f, 0.f, 0.f);
        *(float4*)&xs[rr * XS_STRIDE + cc * 4] = v;
    }
    __syncthreads();

    int r  = tid >> 3;        // 0..31
    int cg = tid & 7;         // 8 cols each
    float acc0[8] = {0,0,0,0,0,0,0,0};
    float acc1[8] = {0,0,0,0,0,0,0,0};
    const float* xr0 = &xs[r * XS_STRIDE];
    const float* xr1 = &xs[(r + 32) * XS_STRIDE];
    #pragma unroll 4
    for (int k = 0; k < NF; k++) {
        float xv0 = xr0[k];
        float xv1 = xr1[k];
        float4 w0 = *(const float4*)&Ws[k * NH + cg * 8];
        float4 w1 = *(const float4*)&Ws[k * NH + cg * 8 + 4];
        acc0[0] += xv0 * w0.x; acc0[1] += xv0 * w0.y;
        acc0[2] += xv0 * w0.z; acc0[3] += xv0 * w0.w;
        acc0[4] += xv0 * w1.x; acc0[5] += xv0 * w1.y;
        acc0[6] += xv0 * w1.z; acc0[7] += xv0 * w1.w;
        acc1[0] += xv1 * w0.x; acc1[1] += xv1 * w0.y;
        acc1[2] += xv1 * w0.z; acc1[3] += xv1 * w0.w;
        acc1[4] += xv1 * w1.x; acc1[5] += xv1 * w1.y;
        acc1[6] += xv1 * w1.z; acc1[7] += xv1 * w1.w;
    }
    int r0g = row0 + r, r1g = row0 + r + 32;
    if (r0g < NN) {
        float* o = g_h1 + (size_t)r0g * NH + cg * 8;
        *(float4*)o       = make_float4(acc0[0], acc0[1], acc0[2], acc0[3]);
        *(float4*)(o + 4) = make_float4(acc0[4], acc0[5], acc0[6], acc0[7]);
    }
    if (r1g < NN) {
        float* o = g_h1 + (size_t)r1g * NH + cg * 8;
        *(float4*)o       = make_float4(acc1[0], acc1[1], acc1[2], acc1[3]);
        *(float4*)(o + 4) = make_float4(acc1[4], acc1[5], acc1[6], acc1[7]);
    }
}

// ---------------- AGG1 (gather, unroll 4) + bias + relu ----------------
__global__ __launch_bounds__(256) void k_agg1(const float* __restrict__ b1) {
    int node = (blockIdx.x * blockDim.x + threadIdx.x) >> 5;
    int lane = threadIdx.x & 31;
    if (node >= NN) return;
    int beg = g_rowptr[node];
    int end = beg + g_cnt[node];
    float di = g_dinv[node];
    float self = di * di;
    const float* hn = &g_h1[(size_t)node * NH];
    float a0 = self * hn[lane];
    float a1 = self * hn[32 + lane];

    int e = beg;
    for (; e + 3 < end; e += 4) {
        int2 e0 = g_edge[e],     e1 = g_edge[e + 1];
        int2 e2 = g_edge[e + 2], e3 = g_edge[e + 3];
        const float* p0 = &g_h1[(size_t)e0.x * NH];
        const float* p1 = &g_h1[(size_t)e1.x * NH];
        const float* p2 = &g_h1[(size_t)e2.x * NH];
        const float* p3 = &g_h1[(size_t)e3.x * NH];
        float v00 = p0[lane], v01 = p0[32 + lane];
        float v10 = p1[lane], v11 = p1[32 + lane];
        float v20 = p2[lane], v21 = p2[32 + lane];
        float v30 = p3[lane], v31 = p3[32 + lane];
        float n0 = __int_as_float(e0.y), n1 = __int_as_float(e1.y);
        float n2 = __int_as_float(e2.y), n3 = __int_as_float(e3.y);
        a0 += n0 * v00; a1 += n0 * v01;
        a0 += n1 * v10; a1 += n1 * v11;
        a0 += n2 * v20; a1 += n2 * v21;
        a0 += n3 * v30; a1 += n3 * v31;
    }
    for (; e < end; e++) {
        int2 ed = g_edge[e];
        const float* p = &g_h1[(size_t)ed.x * NH];
        float n = __int_as_float(ed.y);
        a0 += n * p[lane];
        a1 += n * p[32 + lane];
    }
    a0 += b1[lane];
    a1 += b1[32 + lane];
    g_a1[(size_t)node * NH + lane]      = fmaxf(a0, 0.f);
    g_a1[(size_t)node * NH + 32 + lane] = fmaxf(a1, 0.f);
}

// ---------------- GEMM2: h2 = a1 @ W2  (64 rows/block, k-vectorized) ----------
__global__ __launch_bounds__(256) void k_gemm2(const float* __restrict__ W2) {
    __shared__ float WsT[NC * WT_STRIDE];    // transposed [c][k], padded
    __shared__ float as[64 * AS_STRIDE];     // padded
    int tid = threadIdx.x;
    int row0 = blockIdx.x * 64;

    for (int i = tid; i < NH * NC; i += 256) {
        int k = i / NC, c = i % NC;
        WsT[c * WT_STRIDE + k] = W2[i];
    }
    const float4* a4 = (const float4*)g_a1 + row0 * (NH / 4);
    int limit4 = (NN - row0) * (NH / 4);
    for (int i = tid; i < 64 * (NH / 4); i += 256) {
        int rr = i >> 4;          // i / 16
        int cc = i & 15;
        float4 v = (i < limit4) ? a4[i] : make_float4(0.f, 0.f, 0.f, 0.f);
        *(float4*)&as[rr * AS_STRIDE + cc * 4] = v;
    }
    __syncthreads();

    int r  = tid >> 3;     // 0..31
    int cg = tid & 7;      // 5 cols each -> 40
    float acc0[5] = {0,0,0,0,0};
    float acc1[5] = {0,0,0,0,0};
    const float* ar0 = &as[r * AS_STRIDE];
    const float* ar1 = &as[(r + 32) * AS_STRIDE];
    #pragma unroll
    for (int kk = 0; kk < NH / 4; kk++) {
        float4 av0 = *(const float4*)&ar0[kk * 4];
        float4 av1 = *(const float4*)&ar1[kk * 4];
        #pragma unroll
        for (int j = 0; j < 5; j++) {
            float4 w = *(const float4*)&WsT[(cg * 5 + j) * WT_STRIDE + kk * 4];
            acc0[j] += av0.x * w.x + av0.y * w.y + av0.z * w.z + av0.w * w.w;
            acc1[j] += av1.x * w.x + av1.y * w.y + av1.z * w.z + av1.w * w.w;
        }
    }
    int r0g = row0 + r, r1g = row0 + r + 32;
    if (r0g < NN) {
        float* o = g_h2 + (size_t)r0g * NC + cg * 5;
        #pragma unroll
        for (int j = 0; j < 5; j++) o[j] = acc0[j];
    }
    if (r1g < NN) {
        float* o = g_h2 + (size_t)r1g * NC + cg * 5;
        #pragma unroll
        for (int j = 0; j < 5; j++) o[j] = acc1[j];
    }
}

// ---------------- AGG2 (gather, unroll 4) + bias + log_softmax ----------------
__global__ __launch_bounds__(256) void k_agg2(const float* __restrict__ b2,
                                              float* __restrict__ out) {
    int node = (blockIdx.x * blockDim.x + threadIdx.x) >> 5;
    int lane = threadIdx.x & 31;
    if (node >= NN) return;
    bool hi = (lane < NC - 32);    // lanes 0..7 own cols 32..39
    int beg = g_rowptr[node];
    int end = beg + g_cnt[node];
    float di = g_dinv[node];
    float self = di * di;
    const float* hn = &g_h2[(size_t)node * NC];
    float a0 = self * hn[lane];
    float a1 = hi ? self * hn[32 + lane] : 0.f;

    int e = beg;
    for (; e + 3 < end; e += 4) {
        int2 e0 = g_edge[e],     e1 = g_edge[e + 1];
        int2 e2 = g_edge[e + 2], e3 = g_edge[e + 3];
        const float* p0 = &g_h2[(size_t)e0.x * NC];
        const float* p1 = &g_h2[(size_t)e1.x * NC];
        const float* p2 = &g_h2[(size_t)e2.x * NC];
        const float* p3 = &g_h2[(size_t)e3.x * NC];
        float n0 = __int_as_float(e0.y), n1 = __int_as_float(e1.y);
        float n2 = __int_as_float(e2.y), n3 = __int_as_float(e3.y);
        float v0 = p0[lane], v1 = p1[lane], v2 = p2[lane], v3 = p3[lane];
        a0 += n0 * v0; a0 += n1 * v1; a0 += n2 * v2; a0 += n3 * v3;
        if (hi) {
            float u0 = p0[32 + lane], u1 = p1[32 + lane];
            float u2 = p2[32 + lane], u3 = p3[32 + lane];
            a1 += n0 * u0; a1 += n1 * u1; a1 += n2 * u2; a1 += n3 * u3;
        }
    }
    for (; e < end; e++) {
        int2 ed = g_edge[e];
        const float* p = &g_h2[(size_t)ed.x * NC];
        float n = __int_as_float(ed.y);
        a0 += n * p[lane];
        if (hi) a1 += n * p[32 + lane];
    }
    a0 += b2[lane];
    if (hi) a1 += b2[32 + lane];

    float m = hi ? fmaxf(a0, a1) : a0;
    #pragma unroll
    for (int off = 16; off > 0; off >>= 1)
        m = fmaxf(m, __shfl_xor_sync(0xffffffffu, m, off));
    float s = __expf(a0 - m) + (hi ? __expf(a1 - m) : 0.f);
    #pragma unroll
    for (int off = 16; off > 0; off >>= 1)
        s += __shfl_xor_sync(0xffffffffu, s, off);
    float lse = m + __logf(s);

    float* o = out + (size_t)node * NC;
    o[lane] = a0 - lse;
    if (hi) o[32 + lane] = a1 - lse;
}

// ---------------- launcher ----------------
extern "C" void kernel_launch(void* const* d_in, const int* in_sizes, int n_in,
                              void* d_out, int out_size) {
    const float* x  = (const float*)d_in[0];
    const void*  ei = d_in[1];
    const float* ew = (const float*)d_in[2];
    const float* W1 = (const float*)d_in[3];
    const float* b1 = (const float*)d_in[4];
    const float* W2 = (const float*)d_in[5];
    const float* b2 = (const float*)d_in[6];
    float* out = (float*)d_out;

    const int EB = (NE + 255) / 256;      // 6250
    const int GB = (NN + 63) / 64;        // 1563
    const int AB = (NN * 32 + 255) / 256; // 12500

    void *p_cnt = nullptr, *p_degw = nullptr;
    cudaGetSymbolAddress(&p_cnt,  g_cnt);
    cudaGetSymbolAddress(&p_degw, g_degw);
    cudaMemsetAsync(p_cnt,  0, NN * sizeof(int));
    cudaMemsetAsync(p_degw, 0, NN * sizeof(float));

    k_detect<<<1, 256>>>((const long long*)ei);      // launch 0
    k_decode_deg<<<EB, 256>>>(ei, ew);               // 1
    k_scan1<<<NBLK, SCAN_B>>>();                     // 2
    k_scan2<<<1, 32>>>();                            // 3
    k_scan3<<<NBLK, SCAN_B>>>();                     // 4
    k_gemm1<<<GB, 256>>>(x, W1);                     // 5  <- ncu -s 5 lands here
    k_fill<<<EB, 256>>>(ew);                         // 6
    k_agg1<<<AB, 256>>>(b1);                         // 7
    k_gemm2<<<GB, 256>>>(W2);                        // 8
    k_agg2<<<AB, 256>>>(b2, out);                    // 9
}